// round 5
// baseline (speedup 1.0000x reference)
#include <cuda_runtime.h>
#include <cstdint>
#include <cstddef>

#define TSTEPS 512
#define BATCH  64
#define DIM    512
#define HID    512
#define GDIM   2048            // 4*HID
#define GRID_BLOCKS 64
#define NGRP 8                 // producer groups (= warps per block)
#define JB 8                   // hidden columns per recurrent block
#define WS_STRIDE 516          // padded W staging stride (init only)
#define RED_B 36               // padded partial row stride
#define RED_W (64 * RED_B)     // one warp's partial tile
#define RED_P (8 * RED_W)      // one parity's partial buffer

// ---------------- scratch (static device allocations; no cudaMalloc) -------
__device__ float g_xproj[(size_t)TSTEPS * BATCH * GDIM];  // 256 MB: x@W_ih^T + bias
__device__ float g_hbuf[2][BATCH * HID];                  // ping-pong hidden state
// per-step, per-group arrival counters; each padded to 32B (own sector)
__device__ unsigned g_cnt[(TSTEPS + 1) * NGRP * 8];
#define CNT(t, g) (&g_cnt[(((t) * NGRP) + (g)) * 8])

// ---------------- helpers ---------------------------------------------------
__device__ __forceinline__ float tf32r(float x) {
    uint32_t r; asm("cvt.rna.tf32.f32 %0, %1;" : "=r"(r) : "f"(x));
    return __uint_as_float(r);
}
__device__ __forceinline__ void mma_tf32(float c[4], const uint32_t a[4], const uint32_t b[2]) {
    asm volatile(
        "mma.sync.aligned.m16n8k8.row.col.f32.tf32.tf32.f32 "
        "{%0,%1,%2,%3}, {%4,%5,%6,%7}, {%8,%9}, {%0,%1,%2,%3};"
        : "+f"(c[0]), "+f"(c[1]), "+f"(c[2]), "+f"(c[3])
        : "r"(a[0]), "r"(a[1]), "r"(a[2]), "r"(a[3]), "r"(b[0]), "r"(b[1]));
}
__device__ __forceinline__ float ex2f(float x) { float y; asm("ex2.approx.f32 %0, %1;" : "=f"(y) : "f"(x)); return y; }
__device__ __forceinline__ float rcpf(float x) { float y; asm("rcp.approx.f32 %0, %1;" : "=f"(y) : "f"(x)); return y; }
__device__ __forceinline__ float sigf(float x)  { return rcpf(1.0f + ex2f(-1.4426950408889634f * x)); }
__device__ __forceinline__ float tanhf_(float x){ return 2.0f * sigf(2.0f * x) - 1.0f; }

__device__ __forceinline__ unsigned ld_acq(const unsigned* p) {
    unsigned v; asm volatile("ld.acquire.gpu.global.u32 %0, [%1];" : "=r"(v) : "l"(p)); return v;
}
__device__ __forceinline__ void arrive_release(unsigned* p) {
    asm volatile("red.release.gpu.global.add.u32 [%0], 1;" :: "l"(p) : "memory");
}
__device__ __forceinline__ float ldcg(const float* p) {
    float v; asm volatile("ld.global.cg.f32 %0, [%1];" : "=f"(v) : "l"(p)); return v;
}

// ============================================================================
// Kernel 1: x_proj[m, g] = sum_d X[m,d]*W_ih[g,d] + (b_ih[g]+b_hh[g])
// M = T*B = 32768, K = 512, N = 2048.  TF32 mma.sync, 128x128x32 tiles.
// Also resets the per-step group counters for the lstm kernel that follows.
// ============================================================================
__global__ void __launch_bounds__(256) xproj_kernel(
    const float* __restrict__ X, const float* __restrict__ Wih,
    const float* __restrict__ b_ih, const float* __restrict__ b_hh)
{
    {
        int bid = blockIdx.y * gridDim.x + blockIdx.x;      // 0..4095
        const int ncnt = (TSTEPS + 1) * NGRP;               // 4104
        if (threadIdx.x == 0) {
            if (bid < ncnt) g_cnt[bid * 8] = 0u;
            int b2 = bid + 4096;
            if (b2 < ncnt) g_cnt[b2 * 8] = 0u;
        }
    }

    __shared__ float As[128][36];
    __shared__ float Bs[32][132];

    const int m0 = blockIdx.y * 128;
    const int n0 = blockIdx.x * 128;
    const int tid  = threadIdx.x;
    const int lane = tid & 31;
    const int warp = tid >> 5;
    const int wm = warp >> 1;       // 0..3 : 32 output rows each
    const int wn = warp & 1;        // 0..1 : 64 output cols each
    const int gid = lane >> 2;      // 0..7
    const int tig = lane & 3;       // 0..3

    float acc[2][8][4];
    #pragma unroll
    for (int mt = 0; mt < 2; mt++)
        #pragma unroll
        for (int nt = 0; nt < 8; nt++)
            #pragma unroll
            for (int q = 0; q < 4; q++) acc[mt][nt][q] = 0.0f;

    const int lr = tid >> 3;          // 0..31
    const int lc = (tid & 7) * 4;     // 0..28

    for (int k0 = 0; k0 < DIM; k0 += 32) {
        __syncthreads();
        #pragma unroll
        for (int p = 0; p < 4; p++) {
            int r = lr + p * 32;
            float4 v = *(const float4*)(X + (size_t)(m0 + r) * DIM + k0 + lc);
            As[r][lc+0] = tf32r(v.x); As[r][lc+1] = tf32r(v.y);
            As[r][lc+2] = tf32r(v.z); As[r][lc+3] = tf32r(v.w);
        }
        #pragma unroll
        for (int p = 0; p < 4; p++) {
            int n = lr + p * 32;
            float4 v = *(const float4*)(Wih + (size_t)(n0 + n) * DIM + k0 + lc);
            Bs[lc+0][n] = tf32r(v.x); Bs[lc+1][n] = tf32r(v.y);
            Bs[lc+2][n] = tf32r(v.z); Bs[lc+3][n] = tf32r(v.w);
        }
        __syncthreads();

        #pragma unroll
        for (int ks = 0; ks < 4; ks++) {
            const int kb = ks * 8;
            uint32_t a[2][4], b[8][2];
            #pragma unroll
            for (int mt = 0; mt < 2; mt++) {
                int row = wm * 32 + mt * 16;
                a[mt][0] = __float_as_uint(As[row + gid    ][kb + tig    ]);
                a[mt][1] = __float_as_uint(As[row + gid + 8][kb + tig    ]);
                a[mt][2] = __float_as_uint(As[row + gid    ][kb + tig + 4]);
                a[mt][3] = __float_as_uint(As[row + gid + 8][kb + tig + 4]);
            }
            #pragma unroll
            for (int nt = 0; nt < 8; nt++) {
                int col = wn * 64 + nt * 8 + gid;
                b[nt][0] = __float_as_uint(Bs[kb + tig    ][col]);
                b[nt][1] = __float_as_uint(Bs[kb + tig + 4][col]);
            }
            #pragma unroll
            for (int mt = 0; mt < 2; mt++)
                #pragma unroll
                for (int nt = 0; nt < 8; nt++)
                    mma_tf32(acc[mt][nt], a[mt], b[nt]);
        }
    }

    // epilogue: add bias, write fp32
    #pragma unroll
    for (int mt = 0; mt < 2; mt++) {
        #pragma unroll
        for (int nt = 0; nt < 8; nt++) {
            int row = m0 + wm * 32 + mt * 16 + gid;
            int col = n0 + wn * 64 + nt * 8 + 2 * tig;
            float bz0 = b_ih[col]     + b_hh[col];
            float bz1 = b_ih[col + 1] + b_hh[col + 1];
            float2 v0 = make_float2(acc[mt][nt][0] + bz0, acc[mt][nt][1] + bz1);
            float2 v1 = make_float2(acc[mt][nt][2] + bz0, acc[mt][nt][3] + bz1);
            *(float2*)(g_xproj + (size_t)row       * GDIM + col) = v0;
            *(float2*)(g_xproj + (size_t)(row + 8) * GDIM + col) = v1;
        }
    }
}

// ============================================================================
// Kernel 2: persistent recurrence. Split-K, register-resident W_hh.
// NEW this round:
//  - A-fragments loaded DIRECTLY from g_hbuf via ld.global.cg (each element
//    is consumed exactly once -> SMEM staging was a wasted L2->SMEM->RF hop;
//    .cg bypasses L1, which may hold stale ping-pong lines).
//  - SMEM freed by dropping h_s -> partial buffer `red` is double-buffered
//    by step parity, eliminating the trailing __syncthreads (bar B). One
//    block barrier per step. Safety: reaching the same-parity STS again
//    requires passing next step's bar A, which transitively waits on all
//    readers of the current parity.
// ============================================================================
__global__ void __launch_bounds__(256, 1) lstm_kernel(
    const float* __restrict__ mask, const float* __restrict__ h0,
    const float* __restrict__ Whh, float* __restrict__ out)
{
    extern __shared__ float smem[];
    float* red  = smem;                      // 2 x 8 x 64 x 36 partials (+W staging at init)
    float* h0_s = red  + 2 * RED_P;          // 512
    float* c_s  = h0_s + 512;                // 512

    const int tid  = threadIdx.x;
    const int blk  = blockIdx.x;
    const int j0   = blk * JB;
    const int lane = tid & 31;
    const int warp = tid >> 5;               // 0..7 -> K-slice & poll group
    const int grp  = blk >> 3;               // producer group this block feeds
    const int gid  = lane >> 2;              // 0..7
    const int tig  = lane & 3;               // 0..3
    const int kbase = warp * 64;

    // --- stage W_hh slice (32 rows x 512) into red temporarily, as tf32
    for (int i = tid; i < 32 * 128; i += 256) {
        int r  = i >> 7;                 // 0..31  (gate*8 + jl)
        int k4 = (i & 127) * 4;
        int gate = r >> 3, jl = r & 7;
        float4 v = *(const float4*)(Whh + (size_t)(gate * HID + j0 + jl) * HID + k4);
        float* d = &red[r * WS_STRIDE + k4];
        d[0] = tf32r(v.x); d[1] = tf32r(v.y); d[2] = tf32r(v.z); d[3] = tf32r(v.w);
    }
    // --- h0 slice, c0 = h0; publish tf32-rounded h0 to ping buffer 0
    for (int i = tid; i < 512; i += 256) {
        int b = i >> 3, jl = i & 7;
        float v = h0[b * HID + j0 + jl];
        h0_s[i] = v;
        c_s[i]  = v;
        g_hbuf[0][b * HID + j0 + jl] = tf32r(v);
    }
    __syncthreads();

    // --- preload this warp's B fragments: b[kk][nt][2], resident forever
    uint32_t breg[8][4][2];
    #pragma unroll
    for (int kk = 0; kk < 8; kk++)
        #pragma unroll
        for (int nt = 0; nt < 4; nt++) {
            const float* pb = &red[(nt * 8 + gid) * WS_STRIDE + kbase + kk * 8 + tig];
            breg[kk][nt][0] = __float_as_uint(pb[0]);
            breg[kk][nt][1] = __float_as_uint(pb[4]);
        }
    __syncthreads();
    if (lane == 0) arrive_release(CNT(0, grp));   // h0 published (8 arrivals/block)

    const int rb  = tid >> 2;          // 0..63 batch row for reduce phase
    const int jl0 = (tid & 3) * 2;     // 0,2,4,6

    // prefetch x_proj + mask for t=0
    const float* xp0 = g_xproj + (size_t)rb * GDIM + j0 + jl0;
    float2 xq[4];
    #pragma unroll
    for (int g = 0; g < 4; g++) xq[g] = *(const float2*)(xp0 + g * HID);
    float mval = mask[rb];

    for (int t = 0; t < TSTEPS; t++) {
        const float* hin  = g_hbuf[t & 1];
        float*       hout = g_hbuf[(t + 1) & 1];

        // ---- wait for THIS warp's 8 producer blocks (64 warp-arrivals)
        {
            const unsigned* myc = CNT(t, warp);
            while (ld_acq(myc) < 64u) { }
        }

        // ---- split-K MMA: A-fragments straight from L2 (ld.cg), no staging
        float acc[4][4][4];
        #pragma unroll
        for (int mt = 0; mt < 4; mt++)
            #pragma unroll
            for (int nt = 0; nt < 4; nt++)
                #pragma unroll
                for (int q = 0; q < 4; q++) acc[mt][nt][q] = 0.0f;

        const float* hb = hin + kbase + tig;
        #pragma unroll
        for (int mt = 0; mt < 4; mt++) {
            const float* pr = hb + (size_t)(mt * 16 + gid) * HID;
            uint32_t a[8][4];
            #pragma unroll
            for (int kk = 0; kk < 8; kk++) {
                a[kk][0] = __float_as_uint(ldcg(pr + kk * 8));
                a[kk][1] = __float_as_uint(ldcg(pr + 8 * HID + kk * 8));
                a[kk][2] = __float_as_uint(ldcg(pr + kk * 8 + 4));
                a[kk][3] = __float_as_uint(ldcg(pr + 8 * HID + kk * 8 + 4));
            }
            #pragma unroll
            for (int kk = 0; kk < 8; kk++)
                #pragma unroll
                for (int nt = 0; nt < 4; nt++)
                    mma_tf32(acc[mt][nt], a[kk], breg[kk][nt]);
        }

        // ---- store partials: red[t&1][warp][row][col]
        float* rw = red + (t & 1) * RED_P + warp * RED_W;
        #pragma unroll
        for (int mt = 0; mt < 4; mt++)
            #pragma unroll
            for (int nt = 0; nt < 4; nt++) {
                int row = mt * 16 + gid;
                int col = nt * 8 + 2 * tig;
                float* rp = &rw[row * RED_B + col];
                *(float2*)rp                 = make_float2(acc[mt][nt][0], acc[mt][nt][1]);
                *(float2*)(rp + 8 * RED_B)   = make_float2(acc[mt][nt][2], acc[mt][nt][3]);
            }
        __syncthreads();                       // bar A: partials complete

        // ---- reduce 8 partials + x_proj, LSTM cell, mask blend, publish h
        const float* rbase = red + (t & 1) * RED_P + rb * RED_B + jl0;
        float s[4][2];
        #pragma unroll
        for (int g = 0; g < 4; g++) { s[g][0] = xq[g].x; s[g][1] = xq[g].y; }
        #pragma unroll
        for (int w = 0; w < 8; w++) {
            const float* rr = rbase + w * RED_W;
            #pragma unroll
            for (int g = 0; g < 4; g++) {
                float2 v = *(const float2*)(rr + g * 8);
                s[g][0] += v.x; s[g][1] += v.y;
            }
        }
        float hv[2], cv[2];
        #pragma unroll
        for (int u = 0; u < 2; u++) {
            float iv = sigf(s[0][u]);
            float fv = sigf(s[1][u]);
            float gv = tanhf_(s[2][u]);
            float ov = sigf(s[3][u]);
            int p = rb * 8 + jl0 + u;
            float c = fv * c_s[p] + iv * gv;
            float h = ov * tanhf_(c);
            float z = h0_s[p];                   // h0 == c0
            h = h * mval + z * (1.0f - mval);
            c = c * mval + z * (1.0f - mval);
            c_s[p] = c;
            hv[u] = h; cv[u] = c;
            hout[rb * HID + j0 + jl0 + u] = tf32r(h);
        }
        // this warp's hout rows are stored -> release-arrive immediately
        __syncwarp();
        if (lane == 0) arrive_release(CNT(t + 1, grp));

        // ---- shadow: out[] stores + next-step prefetch (off critical path)
        #pragma unroll
        for (int u = 0; u < 2; u++) {
            int gcol = j0 + jl0 + u;
            out[(size_t)t * BATCH * HID + rb * HID + gcol] = hv[u];
            if (t == TSTEPS - 1) {
                out[(size_t)TSTEPS * BATCH * HID               + rb * HID + gcol] = hv[u];
                out[(size_t)TSTEPS * BATCH * HID + BATCH * HID + rb * HID + gcol] = cv[u];
            }
        }
        if (t + 1 < TSTEPS) {
            const float* xp = g_xproj + (size_t)(t + 1) * BATCH * GDIM
                            + (size_t)rb * GDIM + j0 + jl0;
            #pragma unroll
            for (int g = 0; g < 4; g++) xq[g] = *(const float2*)(xp + g * HID);
            mval = mask[(t + 1) * BATCH + rb];
        }
        // no bar B: red double-buffered by parity; next same-parity write is
        // gated by next step's bar A.
    }
}

// ============================================================================
extern "C" void kernel_launch(void* const* d_in, const int* in_sizes, int n_in,
                              void* d_out, int out_size) {
    const float* inputs = (const float*)d_in[0];   // [512,64,512]
    const float* mask   = (const float*)d_in[1];   // [512,64]
    const float* h0     = (const float*)d_in[2];   // [64,512]
    const float* W_ih   = (const float*)d_in[3];   // [2048,512]
    const float* W_hh   = (const float*)d_in[4];   // [2048,512]
    const float* b_ih   = (const float*)d_in[5];   // [2048]
    const float* b_hh   = (const float*)d_in[6];   // [2048]
    float* out = (float*)d_out;                    // out | hT | cT (fp32)

    const int smem_bytes = (2 * RED_P + 1024 + 32) * 4;
    cudaFuncSetAttribute(lstm_kernel, cudaFuncAttributeMaxDynamicSharedMemorySize, smem_bytes);

    dim3 xg(GDIM / 128, (TSTEPS * BATCH) / 128);   // (16, 256)
    xproj_kernel<<<xg, 256>>>(inputs, W_ih, b_ih, b_hh);

    lstm_kernel<<<GRID_BLOCKS, 256, smem_bytes>>>(mask, h0, W_hh, out);
}

// round 6
// speedup vs baseline: 1.3596x; 1.3596x over previous
#include <cuda_runtime.h>
#include <cstdint>
#include <cstddef>

#define TSTEPS 512
#define BATCH  64
#define DIM    512
#define HID    512
#define GDIM   2048            // 4*HID
#define GRID_BLOCKS 64
#define NGRP 8                 // consumer K-slice groups (= warps per block)
#define JB 8                   // hidden columns per recurrent block
#define HS_STRIDE 516          // padded (512+4) to kill bank conflicts
#define RED_B 36               // padded partial row stride
#define RED_W (64 * RED_B)     // one warp's partial tile

// ---------------- scratch (static device allocations; no cudaMalloc) -------
__device__ float g_xproj[(size_t)TSTEPS * BATCH * GDIM];  // 256 MB: x@W_ih^T + bias
__device__ float g_hbuf[2][BATCH * HID];                  // ping-pong hidden state
// per-group, per-producer-warp monotonic step flags (no atomics):
// g_wflag[grp][ (blk&7)*8 + warp ] holds 1 + latest published h index
__device__ unsigned g_wflag[NGRP * 64];

// ---------------- helpers ---------------------------------------------------
__device__ __forceinline__ float tf32r(float x) {
    uint32_t r; asm("cvt.rna.tf32.f32 %0, %1;" : "=r"(r) : "f"(x));
    return __uint_as_float(r);
}
__device__ __forceinline__ void mma_tf32(float c[4], const uint32_t a[4], const uint32_t b[2]) {
    asm volatile(
        "mma.sync.aligned.m16n8k8.row.col.f32.tf32.tf32.f32 "
        "{%0,%1,%2,%3}, {%4,%5,%6,%7}, {%8,%9}, {%0,%1,%2,%3};"
        : "+f"(c[0]), "+f"(c[1]), "+f"(c[2]), "+f"(c[3])
        : "r"(a[0]), "r"(a[1]), "r"(a[2]), "r"(a[3]), "r"(b[0]), "r"(b[1]));
}
__device__ __forceinline__ float ex2f(float x) { float y; asm("ex2.approx.f32 %0, %1;" : "=f"(y) : "f"(x)); return y; }
__device__ __forceinline__ float rcpf(float x) { float y; asm("rcp.approx.f32 %0, %1;" : "=f"(y) : "f"(x)); return y; }
__device__ __forceinline__ float sigf(float x)  { return rcpf(1.0f + ex2f(-1.4426950408889634f * x)); }
__device__ __forceinline__ float tanhf_(float x){ return 2.0f * sigf(2.0f * x) - 1.0f; }

__device__ __forceinline__ unsigned ld_acq(const unsigned* p) {
    unsigned v; asm volatile("ld.acquire.gpu.global.u32 %0, [%1];" : "=r"(v) : "l"(p)); return v;
}
__device__ __forceinline__ void st_rel(unsigned* p, unsigned v) {
    asm volatile("st.release.gpu.global.u32 [%0], %1;" :: "l"(p), "r"(v) : "memory");
}
__device__ __forceinline__ void cp16(uint32_t s, const void* g) {
    asm volatile("cp.async.cg.shared.global [%0], [%1], 16;" :: "r"(s), "l"(g));
}
__device__ __forceinline__ void cp_wait_all() {
    asm volatile("cp.async.commit_group;\n\tcp.async.wait_group 0;" ::: "memory");
}

// ============================================================================
// Kernel 1: x_proj[m, g] = sum_d X[m,d]*W_ih[g,d] + (b_ih[g]+b_hh[g])
// M = T*B = 32768, K = 512, N = 2048.  TF32 mma.sync, 128x128x32 tiles.
// Also resets the sync flags for the lstm kernel that follows.
// ============================================================================
__global__ void __launch_bounds__(256) xproj_kernel(
    const float* __restrict__ X, const float* __restrict__ Wih,
    const float* __restrict__ b_ih, const float* __restrict__ b_hh)
{
    {
        int bid = blockIdx.y * gridDim.x + blockIdx.x;      // 0..4095
        if (threadIdx.x == 0 && bid < NGRP * 64) g_wflag[bid] = 0u;
    }

    __shared__ float As[128][36];
    __shared__ float Bs[32][132];

    const int m0 = blockIdx.y * 128;
    const int n0 = blockIdx.x * 128;
    const int tid  = threadIdx.x;
    const int lane = tid & 31;
    const int warp = tid >> 5;
    const int wm = warp >> 1;       // 0..3 : 32 output rows each
    const int wn = warp & 1;        // 0..1 : 64 output cols each
    const int gid = lane >> 2;      // 0..7
    const int tig = lane & 3;       // 0..3

    float acc[2][8][4];
    #pragma unroll
    for (int mt = 0; mt < 2; mt++)
        #pragma unroll
        for (int nt = 0; nt < 8; nt++)
            #pragma unroll
            for (int q = 0; q < 4; q++) acc[mt][nt][q] = 0.0f;

    const int lr = tid >> 3;          // 0..31
    const int lc = (tid & 7) * 4;     // 0..28

    for (int k0 = 0; k0 < DIM; k0 += 32) {
        __syncthreads();
        #pragma unroll
        for (int p = 0; p < 4; p++) {
            int r = lr + p * 32;
            float4 v = *(const float4*)(X + (size_t)(m0 + r) * DIM + k0 + lc);
            As[r][lc+0] = tf32r(v.x); As[r][lc+1] = tf32r(v.y);
            As[r][lc+2] = tf32r(v.z); As[r][lc+3] = tf32r(v.w);
        }
        #pragma unroll
        for (int p = 0; p < 4; p++) {
            int n = lr + p * 32;
            float4 v = *(const float4*)(Wih + (size_t)(n0 + n) * DIM + k0 + lc);
            Bs[lc+0][n] = tf32r(v.x); Bs[lc+1][n] = tf32r(v.y);
            Bs[lc+2][n] = tf32r(v.z); Bs[lc+3][n] = tf32r(v.w);
        }
        __syncthreads();

        #pragma unroll
        for (int ks = 0; ks < 4; ks++) {
            const int kb = ks * 8;
            uint32_t a[2][4], b[8][2];
            #pragma unroll
            for (int mt = 0; mt < 2; mt++) {
                int row = wm * 32 + mt * 16;
                a[mt][0] = __float_as_uint(As[row + gid    ][kb + tig    ]);
                a[mt][1] = __float_as_uint(As[row + gid + 8][kb + tig    ]);
                a[mt][2] = __float_as_uint(As[row + gid    ][kb + tig + 4]);
                a[mt][3] = __float_as_uint(As[row + gid + 8][kb + tig + 4]);
            }
            #pragma unroll
            for (int nt = 0; nt < 8; nt++) {
                int col = wn * 64 + nt * 8 + gid;
                b[nt][0] = __float_as_uint(Bs[kb + tig    ][col]);
                b[nt][1] = __float_as_uint(Bs[kb + tig + 4][col]);
            }
            #pragma unroll
            for (int mt = 0; mt < 2; mt++)
                #pragma unroll
                for (int nt = 0; nt < 8; nt++)
                    mma_tf32(acc[mt][nt], a[mt], b[nt]);
        }
    }

    // epilogue: add bias, write fp32
    #pragma unroll
    for (int mt = 0; mt < 2; mt++) {
        #pragma unroll
        for (int nt = 0; nt < 8; nt++) {
            int row = m0 + wm * 32 + mt * 16 + gid;
            int col = n0 + wn * 64 + nt * 8 + 2 * tig;
            float bz0 = b_ih[col]     + b_hh[col];
            float bz1 = b_ih[col + 1] + b_hh[col + 1];
            float2 v0 = make_float2(acc[mt][nt][0] + bz0, acc[mt][nt][1] + bz1);
            float2 v1 = make_float2(acc[mt][nt][2] + bz0, acc[mt][nt][3] + bz1);
            *(float2*)(g_xproj + (size_t)row       * GDIM + col) = v0;
            *(float2*)(g_xproj + (size_t)(row + 8) * GDIM + col) = v1;
        }
    }
}

// ============================================================================
// Kernel 2: persistent recurrence (R4 dataflow) with ATOMIC-FREE flag sync.
// 64 blocks x 256 threads (8 warps). Block owns JB=8 hidden cols across all
// 4 gates. Warp w: K-slice [64w,64w+64), B fragments register-resident.
// Producer block blk / warp v writes h rows 8v..8v+8 of cols 8blk..8blk+8,
// then lane 0 st.release's flag slot [(blk&7)*8+v] of group blk>>3 with t+2.
// Consumer warp w polls group w's 64 flags in ONE vectorized round (2
// ld.acquire per lane + __all_sync). No atomics anywhere per step.
// ============================================================================
__global__ void __launch_bounds__(256, 1) lstm_kernel(
    const float* __restrict__ mask, const float* __restrict__ h0,
    const float* __restrict__ Whh, float* __restrict__ out)
{
    extern __shared__ float smem[];
    float* h_s  = smem;                      // 64 x 516  (also W staging at init)
    float* red  = h_s  + 64 * HS_STRIDE;     // 8 x 64 x 36 partials
    float* h0_s = red  + 8 * RED_W;          // 512
    float* c_s  = h0_s + 512;                // 512

    const int tid  = threadIdx.x;
    const int blk  = blockIdx.x;
    const int j0   = blk * JB;
    const int lane = tid & 31;
    const int warp = tid >> 5;               // 0..7 -> K-slice & poll group
    const int grp  = blk >> 3;               // consumer group this block feeds
    const int slot = (blk & 7) * 8 + warp;   // flag slot within the group
    const int gid  = lane >> 2;              // 0..7
    const int tig  = lane & 3;               // 0..3
    const int kbase = warp * 64;

    // --- stage W_hh slice (32 rows x 512) into h_s temporarily, as tf32
    for (int i = tid; i < 32 * 128; i += 256) {
        int r  = i >> 7;                 // 0..31  (gate*8 + jl)
        int k4 = (i & 127) * 4;
        int gate = r >> 3, jl = r & 7;
        float4 v = *(const float4*)(Whh + (size_t)(gate * HID + j0 + jl) * HID + k4);
        float* d = &h_s[r * HS_STRIDE + k4];
        d[0] = tf32r(v.x); d[1] = tf32r(v.y); d[2] = tf32r(v.z); d[3] = tf32r(v.w);
    }
    // --- h0 slice, c0 = h0; publish tf32-rounded h0 to ping buffer 0
    for (int i = tid; i < 512; i += 256) {
        int b = i >> 3, jl = i & 7;
        float v = h0[b * HID + j0 + jl];
        h0_s[i] = v;
        c_s[i]  = v;
        g_hbuf[0][b * HID + j0 + jl] = tf32r(v);
    }
    __syncthreads();

    // --- preload this warp's B fragments: b[kk][nt][2], resident forever
    uint32_t breg[8][4][2];
    #pragma unroll
    for (int kk = 0; kk < 8; kk++)
        #pragma unroll
        for (int nt = 0; nt < 4; nt++) {
            const float* pb = &h_s[(nt * 8 + gid) * HS_STRIDE + kbase + kk * 8 + tig];
            breg[kk][nt][0] = __float_as_uint(pb[0]);
            breg[kk][nt][1] = __float_as_uint(pb[4]);
        }
    __syncthreads();
    // h0 published: flag value 1  (block's h0 cols were written by ALL threads
    // before the first __syncthreads; every warp signals its slot)
    if (lane == 0) st_rel(&g_wflag[grp * 64 + slot], 1u);

    const int rb  = tid >> 2;          // 0..63 batch row for reduce phase
    const int jl0 = (tid & 3) * 2;     // 0,2,4,6

    // smem byte address for cp.async
    const uint32_t hss = (uint32_t)__cvta_generic_to_shared(h_s);

    // prefetch x_proj + mask for t=0
    const float* xp0 = g_xproj + (size_t)rb * GDIM + j0 + jl0;
    float2 xq[4];
    #pragma unroll
    for (int g = 0; g < 4; g++) xq[g] = *(const float2*)(xp0 + g * HID);
    float mval = mask[rb];

    // this warp's poll addresses (2 flags per lane, 64 total for group `warp`)
    const unsigned* fp = g_wflag + warp * 64;

    for (int t = 0; t < TSTEPS; t++) {
        const float* hin  = g_hbuf[t & 1];
        float*       hout = g_hbuf[(t + 1) & 1];

        // ---- vectorized poll: all 64 producer-warp flags >= t+1
        {
            const unsigned want = (unsigned)(t + 1);
            for (;;) {
                unsigned a = ld_acq(fp + lane);
                unsigned b = ld_acq(fp + lane + 32);
                if (__all_sync(0xffffffffu, a >= want && b >= want)) break;
            }
        }

        // ---- per-warp: cp.async own K-slice [64 rows x 64 cols] into h_s
        {
            const float* src = hin + kbase;
            #pragma unroll 8
            for (int it = 0; it < 32; it++) {
                int e   = it * 32 + lane;
                int row = e >> 4;
                int c4  = (e & 15) << 2;
                cp16(hss + (uint32_t)(row * HS_STRIDE + kbase + c4) * 4,
                     src + (size_t)row * HID + c4);
            }
            cp_wait_all();
            __syncwarp();
        }

        // ---- split-K MMA: this warp covers k in [kbase, kbase+64)
        float acc[4][4][4];
        #pragma unroll
        for (int mt = 0; mt < 4; mt++)
            #pragma unroll
            for (int nt = 0; nt < 4; nt++)
                #pragma unroll
                for (int q = 0; q < 4; q++) acc[mt][nt][q] = 0.0f;

        #pragma unroll
        for (int kk = 0; kk < 8; kk++) {
            uint32_t a[4][4];
            #pragma unroll
            for (int mt = 0; mt < 4; mt++) {
                const float* pa = &h_s[(mt * 16 + gid) * HS_STRIDE + kbase + kk * 8 + tig];
                a[mt][0] = __float_as_uint(pa[0]);
                a[mt][1] = __float_as_uint(pa[8 * HS_STRIDE]);
                a[mt][2] = __float_as_uint(pa[4]);
                a[mt][3] = __float_as_uint(pa[8 * HS_STRIDE + 4]);
            }
            #pragma unroll
            for (int mt = 0; mt < 4; mt++)
                #pragma unroll
                for (int nt = 0; nt < 4; nt++)
                    mma_tf32(acc[mt][nt], a[mt], breg[kk][nt]);
        }

        // ---- store partials: red[warp][row][col]
        float* rw = red + warp * RED_W;
        #pragma unroll
        for (int mt = 0; mt < 4; mt++)
            #pragma unroll
            for (int nt = 0; nt < 4; nt++) {
                int row = mt * 16 + gid;
                int col = nt * 8 + 2 * tig;
                float* rp = &rw[row * RED_B + col];
                *(float2*)rp                 = make_float2(acc[mt][nt][0], acc[mt][nt][1]);
                *(float2*)(rp + 8 * RED_B)   = make_float2(acc[mt][nt][2], acc[mt][nt][3]);
            }
        __syncthreads();                       // bar A: partials complete

        // ---- reduce 8 partials + x_proj, LSTM cell, mask blend, publish h
        float s[4][2];
        #pragma unroll
        for (int g = 0; g < 4; g++) { s[g][0] = xq[g].x; s[g][1] = xq[g].y; }
        #pragma unroll
        for (int w = 0; w < 8; w++) {
            const float* rr = red + w * RED_W + rb * RED_B + jl0;
            #pragma unroll
            for (int g = 0; g < 4; g++) {
                float2 v = *(const float2*)(rr + g * 8);
                s[g][0] += v.x; s[g][1] += v.y;
            }
        }
        float hv[2], cv[2];
        #pragma unroll
        for (int u = 0; u < 2; u++) {
            float iv = sigf(s[0][u]);
            float fv = sigf(s[1][u]);
            float gv = tanhf_(s[2][u]);
            float ov = sigf(s[3][u]);
            int p = rb * 8 + jl0 + u;
            float c = fv * c_s[p] + iv * gv;
            float h = ov * tanhf_(c);
            float z = h0_s[p];                   // h0 == c0
            h = h * mval + z * (1.0f - mval);
            c = c * mval + z * (1.0f - mval);
            c_s[p] = c;
            hv[u] = h; cv[u] = c;
            hout[rb * HID + j0 + jl0 + u] = tf32r(h);
        }
        // this warp's hout rows (batch rows 8*warp..8*warp+8) are stored ->
        // release-publish our flag slot immediately (plain store, no atomic)
        __syncwarp();
        if (lane == 0) st_rel(&g_wflag[grp * 64 + slot], (unsigned)(t + 2));

        // ---- shadow: out[] stores + next-step prefetch (off critical path)
        #pragma unroll
        for (int u = 0; u < 2; u++) {
            int gcol = j0 + jl0 + u;
            out[(size_t)t * BATCH * HID + rb * HID + gcol] = hv[u];
            if (t == TSTEPS - 1) {
                out[(size_t)TSTEPS * BATCH * HID               + rb * HID + gcol] = hv[u];
                out[(size_t)TSTEPS * BATCH * HID + BATCH * HID + rb * HID + gcol] = cv[u];
            }
        }
        if (t + 1 < TSTEPS) {
            const float* xp = g_xproj + (size_t)(t + 1) * BATCH * GDIM
                            + (size_t)rb * GDIM + j0 + jl0;
            #pragma unroll
            for (int g = 0; g < 4; g++) xq[g] = *(const float2*)(xp + g * HID);
            mval = mask[(t + 1) * BATCH + rb];
        }
        __syncthreads();                       // bar B: red safe to overwrite
    }
}

// ============================================================================
extern "C" void kernel_launch(void* const* d_in, const int* in_sizes, int n_in,
                              void* d_out, int out_size) {
    const float* inputs = (const float*)d_in[0];   // [512,64,512]
    const float* mask   = (const float*)d_in[1];   // [512,64]
    const float* h0     = (const float*)d_in[2];   // [64,512]
    const float* W_ih   = (const float*)d_in[3];   // [2048,512]
    const float* W_hh   = (const float*)d_in[4];   // [2048,512]
    const float* b_ih   = (const float*)d_in[5];   // [2048]
    const float* b_hh   = (const float*)d_in[6];   // [2048]
    float* out = (float*)d_out;                    // out | hT | cT (fp32)

    const int smem_bytes = (64 * HS_STRIDE + 8 * RED_W + 1024) * 4;
    cudaFuncSetAttribute(lstm_kernel, cudaFuncAttributeMaxDynamicSharedMemorySize, smem_bytes);

    dim3 xg(GDIM / 128, (TSTEPS * BATCH) / 128);   // (16, 256)
    xproj_kernel<<<xg, 256>>>(inputs, W_ih, b_ih, b_hh);

    lstm_kernel<<<GRID_BLOCKS, 256, smem_bytes>>>(mask, h0, W_hh, out);
}